// round 1
// baseline (speedup 1.0000x reference)
#include <cuda_runtime.h>
#include <math.h>

#define NB      512     // total batch (8*16*4)
#define CHUNK   257
#define NCOEF   771
#define NFRAMES 128
#define STEP    256
#define NSAMP   32768

// Scratch (allocation-free rule: __device__ globals)
__device__ float2 g_spec[(size_t)NB * NFRAMES * CHUNK];  // ~134.7 MB, w_k folded in
__device__ float  g_inv[NB];

// ---------------------------------------------------------------------------
// Kernel A: GEMM (relu(sel) @ items) fused with activation + per-frame
// complex-rotator recurrence. One thread per spectral bin k, 8 batches/CTA.
// ---------------------------------------------------------------------------
#define BPB 8
__global__ void __launch_bounds__(288) kA(const float* __restrict__ sel,
                                          const float* __restrict__ items) {
    __shared__ float sh_sel[BPB * 512];
    const int tid = threadIdx.x;
    const int b0  = blockIdx.x * BPB;

    for (int idx = tid; idx < BPB * 512; idx += 288) {
        float v = sel[b0 * 512 + idx];
        sh_sel[idx] = v > 0.f ? v : 0.f;
    }
    __syncthreads();

    const int k = tid;
    if (k >= CHUNK) return;

    float am[BPB], ap[BPB], as_[BPB];
#pragma unroll
    for (int b = 0; b < BPB; b++) { am[b] = 0.f; ap[b] = 0.f; as_[b] = 0.f; }

    for (int i = 0; i < 512; i++) {
        const float i0 = items[i * NCOEF + k];
        const float i1 = items[i * NCOEF + CHUNK + k];
        const float i2 = items[i * NCOEF + 2 * CHUNK + k];
#pragma unroll
        for (int b = 0; b < BPB; b++) {
            const float s = sh_sel[b * 512 + i];
            am[b]  = fmaf(s, i0, am[b]);
            ap[b]  = fmaf(s, i1, ap[b]);
            as_[b] = fmaf(s, i2, as_[b]);
        }
    }

    // irfft halfcomplex weights folded into spectrum (Im of k=0,256 is dropped
    // later automatically: rotator sin(0)=0 and k=256 handled Re-only).
    const float w = (k == 0 || k == 256) ? (1.f / 512.f) : (2.f / 512.f);

#pragma unroll 1
    for (int b = 0; b < BPB; b++) {
        const float m  = fmaf(1.f / (1.f + expf(-am[b])), 0.9999f * 0.5f, 0.5f);
        const float ph = tanhf(ap[b]) * 3.14159265358979323846f;
        const float st = 1.f / (1.f + expf(-as_[b]));
        float sn, cs;
        sincosf(ph, &sn, &cs);
        const float rRe = m * cs, rIm = m * sn;   // ratio r = m * e^{i ph}
        float cRe = st * rRe, cIm = st * rIm;      // t = 1 term: st * r
        size_t base = ((size_t)(b0 + b) * NFRAMES) * CHUNK + k;
        for (int f = 0; f < NFRAMES; f++) {
            g_spec[base + (size_t)f * CHUNK] = make_float2(w * cRe, w * cIm);
            const float nRe = fmaf(cRe, rRe, -(cIm * rIm));
            const float nIm = fmaf(cRe, rIm,  (cIm * rRe));
            cRe = nRe; cIm = nIm;
        }
    }
}

// ---------------------------------------------------------------------------
// Kernel B: per output block of 256 samples, evaluate two half-frame iDFT
// sums (frame j at n, frame j-1 at n+256) with ONE shared complex rotator.
// (-1)^k for the shifted half is folded via 2x unroll. Hann folded at the end.
// ---------------------------------------------------------------------------
__global__ void __launch_bounds__(256) kB(float* __restrict__ out) {
    __shared__ float4 sh[CHUNK];  // {Re_f, Im_f, Re_{f-1}, Im_{f-1}} per k
    const int tid = threadIdx.x;
    const int j   = blockIdx.x;   // output block / frame index 0..127
    const int b   = blockIdx.y;

    const float2* specF = g_spec + ((size_t)b * NFRAMES + j) * CHUNK;
    const float2* specP = specF - CHUNK;
    for (int k = tid; k < CHUNK; k += 256) {
        const float2 a = specF[k];
        const float2 p = (j > 0) ? specP[k] : make_float2(0.f, 0.f);
        sh[k] = make_float4(a.x, a.y, p.x, p.y);
    }
    __syncthreads();

    float sn, cs;
    sincosf((float)tid * (6.283185307179586f / 512.f), &sn, &cs);
    float c = 1.f, s = 0.f;
    float acc1 = 0.f, acc2 = 0.f;

#pragma unroll 4
    for (int k = 0; k < 256; k += 2) {
        const float4 v = sh[k];            // k even: (+) for shifted half
        acc1 = fmaf(v.x, c, acc1);
        acc1 = fmaf(-v.y, s, acc1);
        acc2 = fmaf(v.z, c, acc2);
        acc2 = fmaf(-v.w, s, acc2);
        const float c1 = fmaf(c, cs, -(s * sn));
        const float s1 = fmaf(s, cs,  (c * sn));
        const float4 u = sh[k + 1];        // k odd: (-) for shifted half
        acc1 = fmaf(u.x, c1, acc1);
        acc1 = fmaf(-u.y, s1, acc1);
        acc2 = fmaf(-u.z, c1, acc2);
        acc2 = fmaf(u.w, s1, acc2);
        c = fmaf(c1, cs, -(s1 * sn));
        s = fmaf(s1, cs,  (c1 * sn));
    }
    // k = 256 (Nyquist): cos = (-1)^n, sin term dropped (halfcomplex).
    const float4 last = sh[256];
    const float par = (tid & 1) ? -1.f : 1.f;
    acc1 = fmaf(last.x, par, acc1);
    acc2 = fmaf(last.z, par, acc2);

    // numpy.hanning(512)[n] = 0.5 - 0.5 cos(2 pi n / 511)
    const float h1 = 0.5f - 0.5f * cosf((float)tid         * (6.283185307179586f / 511.f));
    const float h2 = 0.5f - 0.5f * cosf((float)(tid + 256) * (6.283185307179586f / 511.f));

    out[(size_t)b * NSAMP + j * STEP + tid] = acc1 * h1 + acc2 * h2;
}

// ---------------------------------------------------------------------------
// Kernel C: deterministic per-batch sum of squares -> 1/(||x|| + 1e-8)
// ---------------------------------------------------------------------------
__global__ void __launch_bounds__(256) kC(const float* __restrict__ out) {
    __shared__ float red[256];
    const int b = blockIdx.x, tid = threadIdx.x;
    const float* p = out + (size_t)b * NSAMP;
    float acc = 0.f;
    for (int i = tid; i < NSAMP; i += 256) { const float v = p[i]; acc = fmaf(v, v, acc); }
    red[tid] = acc;
    __syncthreads();
    for (int off = 128; off > 0; off >>= 1) {
        if (tid < off) red[tid] += red[tid + off];
        __syncthreads();
    }
    if (tid == 0) g_inv[b] = 1.f / (sqrtf(red[0]) + 1e-8f);
}

// ---------------------------------------------------------------------------
// Kernel D: scale in place
// ---------------------------------------------------------------------------
__global__ void __launch_bounds__(256) kD(float* __restrict__ out) {
    const size_t idx = (size_t)blockIdx.x * 256 + threadIdx.x;
    out[idx] *= g_inv[idx >> 15];
}

extern "C" void kernel_launch(void* const* d_in, const int* in_sizes, int n_in,
                              void* d_out, int out_size) {
    const float* sel   = (const float*)d_in[0];
    const float* items = (const float*)d_in[1];
    // Defensive: identify inputs by element count (sel=512*512, items=512*771)
    if (n_in >= 2 && in_sizes[0] == 512 * 771) {
        items = (const float*)d_in[0];
        sel   = (const float*)d_in[1];
    }
    float* out = (float*)d_out;

    kA<<<NB / BPB, 288>>>(sel, items);
    kB<<<dim3(NFRAMES, NB), 256>>>(out);
    kC<<<NB, 256>>>(out);
    kD<<<(NB * NSAMP) / 256, 256>>>(out);
}